// round 1
// baseline (speedup 1.0000x reference)
#include <cuda_runtime.h>
#include <math.h>

// ---------------- problem constants ----------------
#define NLAYER 4
#define NHEAD  8
#define DMODEL 512
#define TLEN   2048
#define BATCH  2
#define VOCAB  32000
#define HDIM   64
#define MROWS  (BATCH * TLEN)   // 4096
#define EPS    1e-5f

// ---------------- scratch (static device globals; no allocs allowed) -------
__device__ float g_x  [MROWS * DMODEL];        // residual stream
__device__ float g_h  [MROWS * DMODEL];        // layernorm output
__device__ float g_qkv[MROWS * 3 * DMODEL];    // qkv projection
__device__ float g_att[MROWS * DMODEL];        // attention output (pre-proj)
__device__ float g_fc [MROWS * 4 * DMODEL];    // mlp hidden

// ---------------- embedding: x = wte[idx] + wpe[t] --------------------------
__global__ void embed_kernel(const float* __restrict__ wte,
                             const float* __restrict__ wpe,
                             const int*   __restrict__ idx,
                             float* __restrict__ x) {
    int m = blockIdx.x;            // 0..4095
    int t = m % TLEN;
    int tok = idx[m];
    const float* we = wte + (size_t)tok * DMODEL;
    const float* pe = wpe + (size_t)t * DMODEL;
    float* xr = x + (size_t)m * DMODEL;
    for (int d = threadIdx.x; d < DMODEL; d += blockDim.x)
        xr[d] = we[d] + pe[d];
}

// ---------------- layernorm (two-pass mean/var, matches reference) ----------
__global__ __launch_bounds__(256)
void ln_kernel(const float* __restrict__ x, const float* __restrict__ w,
               const float* __restrict__ b, float* __restrict__ y) {
    int row = blockIdx.x;
    int tid = threadIdx.x;
    const float* xr = x + (size_t)row * DMODEL;
    float v0 = xr[tid];
    float v1 = xr[tid + 256];

    __shared__ float red[8];
    __shared__ float bc;

    float s = v0 + v1;
    #pragma unroll
    for (int o = 16; o; o >>= 1) s += __shfl_xor_sync(0xffffffffu, s, o);
    if ((tid & 31) == 0) red[tid >> 5] = s;
    __syncthreads();
    if (tid == 0) {
        float t = 0.f;
        #pragma unroll
        for (int i = 0; i < 8; i++) t += red[i];
        bc = t;
    }
    __syncthreads();
    float mu = bc * (1.f / DMODEL);
    float d0 = v0 - mu, d1 = v1 - mu;

    float s2 = d0 * d0 + d1 * d1;
    #pragma unroll
    for (int o = 16; o; o >>= 1) s2 += __shfl_xor_sync(0xffffffffu, s2, o);
    __syncthreads();                       // protect red/bc reuse
    if ((tid & 31) == 0) red[tid >> 5] = s2;
    __syncthreads();
    if (tid == 0) {
        float t = 0.f;
        #pragma unroll
        for (int i = 0; i < 8; i++) t += red[i];
        bc = t;
    }
    __syncthreads();
    float inv = rsqrtf(bc * (1.f / DMODEL) + EPS);

    float* yr = y + (size_t)row * DMODEL;
    yr[tid]       = d0 * inv * w[tid]       + b[tid];
    yr[tid + 256] = d1 * inv * w[tid + 256] + b[tid + 256];
}

// ---------------- SGEMM: C[M,N] = A[M,K] @ B + bias (+resid) (opt gelu) -----
// BTRANS=false: B is [K,N] row-major.  BTRANS=true: B is [N,K] row-major (B^T).
// 128x128 block tile, BK=16, 256 threads, 8x8 microtile per thread.
template<bool BTRANS>
__global__ __launch_bounds__(256)
void sgemm_kernel(const float* __restrict__ A, const float* __restrict__ Bm,
                  const float* __restrict__ bias, const float* __restrict__ resid,
                  float* __restrict__ Cm, int M, int N, int K, int gelu_flag) {
    const int BK = 16;
    __shared__ float As[BK][128];
    __shared__ float Bs[BK][128];

    int tid = threadIdx.x;
    int tx = tid & 15;        // 0..15 -> n microtile
    int ty = tid >> 4;        // 0..15 -> m microtile
    int m0 = blockIdx.y * 128;
    int n0 = blockIdx.x * 128;

    float acc[8][8];
    #pragma unroll
    for (int i = 0; i < 8; i++)
        #pragma unroll
        for (int j = 0; j < 8; j++) acc[i][j] = 0.f;

    for (int k0 = 0; k0 < K; k0 += BK) {
        // load A tile (128 x 16), transpose into As[k][m]
        #pragma unroll
        for (int s = 0; s < 2; s++) {
            int idx = tid + s * 256;        // 0..511 float4s
            int r = idx >> 2;               // 0..127 row in tile
            int c = (idx & 3) * 4;          // k offset
            float4 av = *(const float4*)&A[(size_t)(m0 + r) * K + k0 + c];
            As[c + 0][r] = av.x; As[c + 1][r] = av.y;
            As[c + 2][r] = av.z; As[c + 3][r] = av.w;
        }
        // load B tile into Bs[k][n]
        if (!BTRANS) {
            #pragma unroll
            for (int s = 0; s < 2; s++) {
                int idx = tid + s * 256;
                int r  = idx >> 5;          // 0..15 k row
                int c4 = idx & 31;          // float4 col
                float4 bv = *(const float4*)&Bm[(size_t)(k0 + r) * N + n0 + c4 * 4];
                *(float4*)&Bs[r][c4 * 4] = bv;
            }
        } else {
            #pragma unroll
            for (int s = 0; s < 2; s++) {
                int idx = tid + s * 256;
                int r = idx >> 2;           // 0..127 n row
                int c = (idx & 3) * 4;      // k offset
                float4 bv = *(const float4*)&Bm[(size_t)(n0 + r) * K + k0 + c];
                Bs[c + 0][r] = bv.x; Bs[c + 1][r] = bv.y;
                Bs[c + 2][r] = bv.z; Bs[c + 3][r] = bv.w;
            }
        }
        __syncthreads();

        #pragma unroll
        for (int kk = 0; kk < BK; kk++) {
            float a[8], b[8];
            *(float4*)&a[0] = *(float4*)&As[kk][ty * 8];
            *(float4*)&a[4] = *(float4*)&As[kk][ty * 8 + 4];
            *(float4*)&b[0] = *(float4*)&Bs[kk][tx * 8];
            *(float4*)&b[4] = *(float4*)&Bs[kk][tx * 8 + 4];
            #pragma unroll
            for (int i = 0; i < 8; i++)
                #pragma unroll
                for (int j = 0; j < 8; j++)
                    acc[i][j] += a[i] * b[j];
        }
        __syncthreads();
    }

    // epilogue
    #pragma unroll
    for (int i = 0; i < 8; i++) {
        int m = m0 + ty * 8 + i;
        float* crow = Cm + (size_t)m * N;
        const float* rrow = resid ? resid + (size_t)m * N : nullptr;
        #pragma unroll
        for (int j = 0; j < 8; j++) {
            int n = n0 + tx * 8 + j;
            float c = acc[i][j];
            if (bias)  c += bias[n];
            if (rrow)  c += rrow[n];
            if (gelu_flag) c = 0.5f * c * (1.f + erff(c * 0.70710678118654752f));
            crow[n] = c;
        }
    }
}

// ---------------- causal flash attention (fp32, 64x64 tiles) ----------------
// grid: (TLEN/64, BATCH*NHEAD), 256 threads. Dynamic smem ~67KB.
#define ATTN_P 65  // smem row pitch
__global__ __launch_bounds__(256)
void attn_kernel(const float* __restrict__ qkv, float* __restrict__ out) {
    extern __shared__ float sm[];
    float* Qs  = sm;                     // [64][65]
    float* Ks  = Qs + 64 * ATTN_P;       // [64][65]
    float* Vs  = Ks + 64 * ATTN_P;       // [64][65]
    float* Ss  = Vs + 64 * ATTN_P;       // [64][65]
    float* m_s = Ss + 64 * ATTN_P;       // [64]
    float* l_s = m_s + 64;               // [64]
    float* f_s = l_s + 64;               // [64]

    int tid = threadIdx.x;
    int ty = tid >> 4;   // query group (rows 4*ty..4*ty+3)
    int tx = tid & 15;   // key/dim group (cols 4*tx..4*tx+3)
    int bh = blockIdx.y;
    int b = bh / NHEAD, h = bh % NHEAD;
    int q0 = blockIdx.x * 64;
    const int RS = 3 * DMODEL;           // qkv row stride
    size_t base = (size_t)b * TLEN * RS;
    const float* qbase = qkv + base + (size_t)h * HDIM;
    const float* kbase = qbase + DMODEL;
    const float* vbase = qbase + 2 * DMODEL;
    const float scale = 0.125f;          // 1/sqrt(64)

    // load Q tile
    for (int i = tid; i < 64 * 64; i += 256) {
        int r = i >> 6, d = i & 63;
        Qs[r * ATTN_P + d] = qbase[(size_t)(q0 + r) * RS + d];
    }
    if (tid < 64) { m_s[tid] = -1e30f; l_s[tid] = 0.f; }

    float o[4][4];
    #pragma unroll
    for (int i = 0; i < 4; i++)
        #pragma unroll
        for (int j = 0; j < 4; j++) o[i][j] = 0.f;

    for (int j0 = 0; j0 <= q0; j0 += 64) {
        // load K,V tiles
        for (int i = tid; i < 64 * 64; i += 256) {
            int r = i >> 6, d = i & 63;
            Ks[r * ATTN_P + d] = kbase[(size_t)(j0 + r) * RS + d];
            Vs[r * ATTN_P + d] = vbase[(size_t)(j0 + r) * RS + d];
        }
        __syncthreads();

        // S = (Q K^T) * scale, causal mask
        float acc[4][4];
        #pragma unroll
        for (int i = 0; i < 4; i++)
            #pragma unroll
            for (int j = 0; j < 4; j++) acc[i][j] = 0.f;
        const float* qp = Qs + (4 * ty) * ATTN_P;
        const float* kp = Ks + (4 * tx) * ATTN_P;
        #pragma unroll 4
        for (int d = 0; d < 64; d++) {
            float q0v = qp[d], q1v = qp[ATTN_P + d],
                  q2v = qp[2 * ATTN_P + d], q3v = qp[3 * ATTN_P + d];
            float k0v = kp[d], k1v = kp[ATTN_P + d],
                  k2v = kp[2 * ATTN_P + d], k3v = kp[3 * ATTN_P + d];
            acc[0][0] += q0v * k0v; acc[0][1] += q0v * k1v; acc[0][2] += q0v * k2v; acc[0][3] += q0v * k3v;
            acc[1][0] += q1v * k0v; acc[1][1] += q1v * k1v; acc[1][2] += q1v * k2v; acc[1][3] += q1v * k3v;
            acc[2][0] += q2v * k0v; acc[2][1] += q2v * k1v; acc[2][2] += q2v * k2v; acc[2][3] += q2v * k3v;
            acc[3][0] += q3v * k0v; acc[3][1] += q3v * k1v; acc[3][2] += q3v * k2v; acc[3][3] += q3v * k3v;
        }
        #pragma unroll
        for (int i = 0; i < 4; i++) {
            int qq = q0 + 4 * ty + i;
            #pragma unroll
            for (int j = 0; j < 4; j++) {
                int kk = j0 + 4 * tx + j;
                float s = acc[i][j] * scale;
                if (kk > qq) s = -1e30f;
                Ss[(4 * ty + i) * ATTN_P + 4 * tx + j] = s;
            }
        }
        __syncthreads();

        // per-row online softmax (threads 0..63)
        if (tid < 64) {
            int r = tid;
            float mold = m_s[r];
            float mx = mold;
            float* srow = Ss + r * ATTN_P;
            #pragma unroll 8
            for (int k = 0; k < 64; k++) mx = fmaxf(mx, srow[k]);
            float fac = __expf(mold - mx);
            float l = l_s[r] * fac;
            #pragma unroll 8
            for (int k = 0; k < 64; k++) {
                float p = __expf(srow[k] - mx);
                srow[k] = p;
                l += p;
            }
            m_s[r] = mx; l_s[r] = l; f_s[r] = fac;
        }
        __syncthreads();

        // O = O*fac + P @ V
        #pragma unroll
        for (int i = 0; i < 4; i++) {
            float f = f_s[4 * ty + i];
            #pragma unroll
            for (int j = 0; j < 4; j++) o[i][j] *= f;
        }
        const float* sp = Ss + (4 * ty) * ATTN_P;
        #pragma unroll 4
        for (int k = 0; k < 64; k++) {
            float p0 = sp[k], p1 = sp[ATTN_P + k],
                  p2 = sp[2 * ATTN_P + k], p3 = sp[3 * ATTN_P + k];
            const float* vrow = Vs + k * ATTN_P + 4 * tx;
            float v0 = vrow[0], v1 = vrow[1], v2 = vrow[2], v3 = vrow[3];
            o[0][0] += p0 * v0; o[0][1] += p0 * v1; o[0][2] += p0 * v2; o[0][3] += p0 * v3;
            o[1][0] += p1 * v0; o[1][1] += p1 * v1; o[1][2] += p1 * v2; o[1][3] += p1 * v3;
            o[2][0] += p2 * v0; o[2][1] += p2 * v1; o[2][2] += p2 * v2; o[2][3] += p2 * v3;
            o[3][0] += p3 * v0; o[3][1] += p3 * v1; o[3][2] += p3 * v2; o[3][3] += p3 * v3;
        }
        __syncthreads();
    }

    // finalize
    #pragma unroll
    for (int i = 0; i < 4; i++) {
        float inv = 1.f / l_s[4 * ty + i];
        size_t orow = (size_t)(b * TLEN + q0 + 4 * ty + i) * DMODEL + h * HDIM + 4 * tx;
        #pragma unroll
        for (int j = 0; j < 4; j++)
            out[orow + j] = o[i][j] * inv;
    }
}

#define ATTN_SMEM ((4 * 64 * ATTN_P + 3 * 64) * (int)sizeof(float))

// ---------------- driver ----------------------------------------------------
extern "C" void kernel_launch(void* const* d_in, const int* in_sizes, int n_in,
                              void* d_out, int out_size) {
    const float* wte    = (const float*)d_in[0];
    const float* wpe    = (const float*)d_in[1];
    const float* ln1_w  = (const float*)d_in[2];
    const float* ln1_b  = (const float*)d_in[3];
    const float* attn_w = (const float*)d_in[4];
    const float* attn_b = (const float*)d_in[5];
    const float* proj_w = (const float*)d_in[6];
    const float* proj_b = (const float*)d_in[7];
    const float* ln2_w  = (const float*)d_in[8];
    const float* ln2_b  = (const float*)d_in[9];
    const float* fc_w   = (const float*)d_in[10];
    const float* fc_b   = (const float*)d_in[11];
    const float* fc2_w  = (const float*)d_in[12];
    const float* fc2_b  = (const float*)d_in[13];
    const float* lnf_w  = (const float*)d_in[14];
    const float* lnf_b  = (const float*)d_in[15];
    const int*   idx    = (const int*)d_in[16];
    float* out = (float*)d_out;

    void *px, *ph, *pqkv, *patt, *pfc;
    cudaGetSymbolAddress(&px, g_x);
    cudaGetSymbolAddress(&ph, g_h);
    cudaGetSymbolAddress(&pqkv, g_qkv);
    cudaGetSymbolAddress(&patt, g_att);
    cudaGetSymbolAddress(&pfc, g_fc);
    float* x   = (float*)px;
    float* h   = (float*)ph;
    float* qkv = (float*)pqkv;
    float* att = (float*)patt;
    float* fcb = (float*)pfc;

    cudaFuncSetAttribute(attn_kernel,
                         cudaFuncAttributeMaxDynamicSharedMemorySize, ATTN_SMEM);

    embed_kernel<<<MROWS, 256>>>(wte, wpe, idx, x);

    for (int l = 0; l < NLAYER; l++) {
        const float* aw  = attn_w + (size_t)l * DMODEL * 3 * DMODEL;
        const float* ab  = attn_b + (size_t)l * 3 * DMODEL;
        const float* pw  = proj_w + (size_t)l * DMODEL * DMODEL;
        const float* pb  = proj_b + (size_t)l * DMODEL;
        const float* fw  = fc_w   + (size_t)l * DMODEL * 4 * DMODEL;
        const float* fb  = fc_b   + (size_t)l * 4 * DMODEL;
        const float* f2w = fc2_w  + (size_t)l * 4 * DMODEL * DMODEL;
        const float* f2b = fc2_b  + (size_t)l * DMODEL;

        // h = LN1(x)
        ln_kernel<<<MROWS, 256>>>(x, ln1_w + l * DMODEL, ln1_b + l * DMODEL, h);
        // qkv = h @ attn_w + attn_b
        sgemm_kernel<false><<<dim3(3 * DMODEL / 128, MROWS / 128), 256>>>(
            h, aw, ab, nullptr, qkv, MROWS, 3 * DMODEL, DMODEL, 0);
        // att = causal_attention(qkv)
        attn_kernel<<<dim3(TLEN / 64, BATCH * NHEAD), 256, ATTN_SMEM>>>(qkv, att);
        // x = x + att @ proj_w + proj_b
        sgemm_kernel<false><<<dim3(DMODEL / 128, MROWS / 128), 256>>>(
            att, pw, pb, x, x, MROWS, DMODEL, DMODEL, 0);
        // h = LN2(x)
        ln_kernel<<<MROWS, 256>>>(x, ln2_w + l * DMODEL, ln2_b + l * DMODEL, h);
        // fcb = gelu(h @ fc_w + fc_b)
        sgemm_kernel<false><<<dim3(4 * DMODEL / 128, MROWS / 128), 256>>>(
            h, fw, fb, nullptr, fcb, MROWS, 4 * DMODEL, DMODEL, 1);
        // x = x + fcb @ fc2_w + fc2_b
        sgemm_kernel<false><<<dim3(DMODEL / 128, MROWS / 128), 256>>>(
            fcb, f2w, f2b, x, x, MROWS, DMODEL, 4 * DMODEL, 0);
    }

    // h = LNf(x); out = h @ wte^T
    ln_kernel<<<MROWS, 256>>>(x, lnf_w, lnf_b, h);
    sgemm_kernel<true><<<dim3(VOCAB / 128, MROWS / 128), 256>>>(
        h, wte, nullptr, nullptr, out, MROWS, VOCAB, DMODEL, 0);
}

// round 2
// speedup vs baseline: 1.9366x; 1.9366x over previous
#include <cuda_runtime.h>
#include <math.h>
#include <stdint.h>

// ---------------- problem constants ----------------
#define NLAYER 4
#define NHEAD  8
#define DMODEL 512
#define TLEN   2048
#define BATCH  2
#define VOCAB  32000
#define HDIM   64
#define MROWS  (BATCH * TLEN)   // 4096
#define EPS    1e-5f

// ---------------- scratch (static device globals; no allocs allowed) -------
__device__ float g_x  [MROWS * DMODEL];        // residual stream
__device__ float g_h  [MROWS * DMODEL];        // layernorm output
__device__ float g_qkv[MROWS * 3 * DMODEL];    // qkv projection
__device__ float g_att[MROWS * DMODEL];        // attention output (pre-proj)
__device__ float g_fc [MROWS * 4 * DMODEL];    // mlp hidden

// ---------------- embedding: x = wte[idx] + wpe[t] --------------------------
__global__ void embed_kernel(const float* __restrict__ wte,
                             const float* __restrict__ wpe,
                             const int*   __restrict__ idx,
                             float* __restrict__ x) {
    int m = blockIdx.x;
    int t = m % TLEN;
    int tok = idx[m];
    const float* we = wte + (size_t)tok * DMODEL;
    const float* pe = wpe + (size_t)t * DMODEL;
    float* xr = x + (size_t)m * DMODEL;
    for (int d = threadIdx.x; d < DMODEL; d += blockDim.x)
        xr[d] = we[d] + pe[d];
}

// ---------------- layernorm ----------------
__global__ __launch_bounds__(256)
void ln_kernel(const float* __restrict__ x, const float* __restrict__ w,
               const float* __restrict__ b, float* __restrict__ y) {
    int row = blockIdx.x;
    int tid = threadIdx.x;
    const float* xr = x + (size_t)row * DMODEL;
    float v0 = xr[tid];
    float v1 = xr[tid + 256];

    __shared__ float red[8];
    __shared__ float bc;

    float s = v0 + v1;
    #pragma unroll
    for (int o = 16; o; o >>= 1) s += __shfl_xor_sync(0xffffffffu, s, o);
    if ((tid & 31) == 0) red[tid >> 5] = s;
    __syncthreads();
    if (tid == 0) {
        float t = 0.f;
        #pragma unroll
        for (int i = 0; i < 8; i++) t += red[i];
        bc = t;
    }
    __syncthreads();
    float mu = bc * (1.f / DMODEL);
    float d0 = v0 - mu, d1 = v1 - mu;

    float s2 = d0 * d0 + d1 * d1;
    #pragma unroll
    for (int o = 16; o; o >>= 1) s2 += __shfl_xor_sync(0xffffffffu, s2, o);
    __syncthreads();
    if ((tid & 31) == 0) red[tid >> 5] = s2;
    __syncthreads();
    if (tid == 0) {
        float t = 0.f;
        #pragma unroll
        for (int i = 0; i < 8; i++) t += red[i];
        bc = t;
    }
    __syncthreads();
    float inv = rsqrtf(bc * (1.f / DMODEL) + EPS);

    float* yr = y + (size_t)row * DMODEL;
    yr[tid]       = d0 * inv * w[tid]       + b[tid];
    yr[tid + 256] = d1 * inv * w[tid + 256] + b[tid + 256];
}

// ---------------- tf32 helpers ----------------------------------------------
__device__ __forceinline__ uint32_t f2tf32(float v) {
    uint32_t r;
    asm("cvt.rna.tf32.f32 %0, %1;" : "=r"(r) : "f"(v));
    return r;
}

__device__ __forceinline__ void mma_tf32(float* d, const uint32_t* a, const uint32_t* b) {
    asm volatile(
        "mma.sync.aligned.m16n8k8.row.col.f32.tf32.tf32.f32 "
        "{%0,%1,%2,%3},{%4,%5,%6,%7},{%8,%9},{%0,%1,%2,%3};\n"
        : "+f"(d[0]), "+f"(d[1]), "+f"(d[2]), "+f"(d[3])
        : "r"(a[0]), "r"(a[1]), "r"(a[2]), "r"(a[3]), "r"(b[0]), "r"(b[1]));
}

// ---------------- tf32 tensor-core GEMM -------------------------------------
// C[M,N] = A[M,K] @ B (+bias) (+resid) (opt gelu).
// BTRANS=false: B is [K,N] row-major. BTRANS=true: B is [N,K] row-major.
// 128x128 block tile, BK=16, 256 threads = 8 warps (2 Mwarps x 4 Nwarps),
// warp tile 64x32, mma m16n8k8 (4 mi x 4 nj per warp per k-step of 8).
// Smem layouts chosen conflict-free for fragment loads:
//   As[m][k]: pitch 20  -> a-frag addr (g*20+tig) covers all 32 banks
//   Bs[k][n]: pitch 136 -> b-frag addr (tig*8+g)  covers all 32 banks
#define AP 20
#define BP 136
template<bool BTRANS>
__global__ __launch_bounds__(256)
void gemm_tf32(const float* __restrict__ A, const float* __restrict__ Bm,
               const float* __restrict__ bias, const float* __restrict__ resid,
               float* __restrict__ Cm, int M, int N, int K, int gelu_flag) {
    __shared__ uint32_t As[128 * AP];
    __shared__ uint32_t Bs[16 * BP];

    int tid  = threadIdx.x;
    int lane = tid & 31;
    int w    = tid >> 5;
    int g    = lane >> 2;      // 0..7
    int tig  = lane & 3;       // 0..3
    int wm   = (w >> 2) * 64;  // warp M offset: 0 or 64
    int wn   = (w & 3) * 32;   // warp N offset: 0,32,64,96
    int m0 = blockIdx.y * 128;
    int n0 = blockIdx.x * 128;

    float d[4][4][4];
    #pragma unroll
    for (int i = 0; i < 4; i++)
        #pragma unroll
        for (int j = 0; j < 4; j++)
            #pragma unroll
            for (int r = 0; r < 4; r++) d[i][j][r] = 0.f;

    for (int k0 = 0; k0 < K; k0 += 16) {
        // ---- load A tile (128 x 16) into As[m][k], tf32-rounded
        #pragma unroll
        for (int s = 0; s < 2; s++) {
            int idx = tid + s * 256;        // 0..511 float4s
            int r = idx >> 2;               // 0..127
            int c = (idx & 3) * 4;          // k offset
            float4 av = *(const float4*)&A[(size_t)(m0 + r) * K + k0 + c];
            As[r * AP + c + 0] = f2tf32(av.x);
            As[r * AP + c + 1] = f2tf32(av.y);
            As[r * AP + c + 2] = f2tf32(av.z);
            As[r * AP + c + 3] = f2tf32(av.w);
        }
        // ---- load B tile (16 x 128) into Bs[k][n], tf32-rounded
        if (!BTRANS) {
            #pragma unroll
            for (int s = 0; s < 2; s++) {
                int idx = tid + s * 256;
                int r  = idx >> 5;          // 0..15
                int c4 = idx & 31;
                float4 bv = *(const float4*)&Bm[(size_t)(k0 + r) * N + n0 + c4 * 4];
                uint32_t* p = &Bs[r * BP + c4 * 4];
                p[0] = f2tf32(bv.x); p[1] = f2tf32(bv.y);
                p[2] = f2tf32(bv.z); p[3] = f2tf32(bv.w);
            }
        } else {
            #pragma unroll
            for (int s = 0; s < 2; s++) {
                int idx = tid + s * 256;
                int r = idx >> 2;           // 0..127 (n row)
                int c = (idx & 3) * 4;      // k offset
                float4 bv = *(const float4*)&Bm[(size_t)(n0 + r) * K + k0 + c];
                Bs[(c + 0) * BP + r] = f2tf32(bv.x);
                Bs[(c + 1) * BP + r] = f2tf32(bv.y);
                Bs[(c + 2) * BP + r] = f2tf32(bv.z);
                Bs[(c + 3) * BP + r] = f2tf32(bv.w);
            }
        }
        __syncthreads();

        #pragma unroll
        for (int kk = 0; kk < 16; kk += 8) {
            uint32_t af[4][4];
            #pragma unroll
            for (int mi = 0; mi < 4; mi++) {
                int rb = wm + mi * 16;
                af[mi][0] = As[(rb + g    ) * AP + kk + tig    ];
                af[mi][1] = As[(rb + g + 8) * AP + kk + tig    ];
                af[mi][2] = As[(rb + g    ) * AP + kk + tig + 4];
                af[mi][3] = As[(rb + g + 8) * AP + kk + tig + 4];
            }
            uint32_t bf[4][2];
            #pragma unroll
            for (int nj = 0; nj < 4; nj++) {
                int cb = wn + nj * 8;
                bf[nj][0] = Bs[(kk + tig    ) * BP + cb + g];
                bf[nj][1] = Bs[(kk + tig + 4) * BP + cb + g];
            }
            #pragma unroll
            for (int mi = 0; mi < 4; mi++)
                #pragma unroll
                for (int nj = 0; nj < 4; nj++)
                    mma_tf32(d[mi][nj], af[mi], bf[nj]);
        }
        __syncthreads();
    }

    // ---- epilogue: c0,c1 -> row g, cols 2t,2t+1; c2,c3 -> row g+8
    #pragma unroll
    for (int mi = 0; mi < 4; mi++) {
        #pragma unroll
        for (int rr = 0; rr < 2; rr++) {
            int m = m0 + wm + mi * 16 + g + rr * 8;
            float* crow = Cm + (size_t)m * N;
            const float* rrow = resid ? resid + (size_t)m * N : nullptr;
            #pragma unroll
            for (int nj = 0; nj < 4; nj++) {
                int n = n0 + wn + nj * 8 + tig * 2;
                #pragma unroll
                for (int cc = 0; cc < 2; cc++) {
                    float c = d[mi][nj][rr * 2 + cc];
                    if (bias) c += bias[n + cc];
                    if (rrow) c += rrow[n + cc];
                    if (gelu_flag)
                        c = 0.5f * c * (1.f + erff(c * 0.70710678118654752f));
                    crow[n + cc] = c;
                }
            }
        }
    }
}

// ---------------- causal flash attention (fp32, 64x64 tiles) ----------------
#define ATTN_P 65
__global__ __launch_bounds__(256)
void attn_kernel(const float* __restrict__ qkv, float* __restrict__ out) {
    extern __shared__ float sm[];
    float* Qs  = sm;
    float* Ks  = Qs + 64 * ATTN_P;
    float* Vs  = Ks + 64 * ATTN_P;
    float* Ss  = Vs + 64 * ATTN_P;
    float* m_s = Ss + 64 * ATTN_P;
    float* l_s = m_s + 64;
    float* f_s = l_s + 64;

    int tid = threadIdx.x;
    int ty = tid >> 4;
    int tx = tid & 15;
    int bh = blockIdx.y;
    int b = bh / NHEAD, h = bh % NHEAD;
    int q0 = blockIdx.x * 64;
    const int RS = 3 * DMODEL;
    size_t base = (size_t)b * TLEN * RS;
    const float* qbase = qkv + base + (size_t)h * HDIM;
    const float* kbase = qbase + DMODEL;
    const float* vbase = qbase + 2 * DMODEL;
    const float scale = 0.125f;

    for (int i = tid; i < 64 * 64; i += 256) {
        int r = i >> 6, dd = i & 63;
        Qs[r * ATTN_P + dd] = qbase[(size_t)(q0 + r) * RS + dd];
    }
    if (tid < 64) { m_s[tid] = -1e30f; l_s[tid] = 0.f; }

    float o[4][4];
    #pragma unroll
    for (int i = 0; i < 4; i++)
        #pragma unroll
        for (int j = 0; j < 4; j++) o[i][j] = 0.f;

    for (int j0 = 0; j0 <= q0; j0 += 64) {
        for (int i = tid; i < 64 * 64; i += 256) {
            int r = i >> 6, dd = i & 63;
            Ks[r * ATTN_P + dd] = kbase[(size_t)(j0 + r) * RS + dd];
            Vs[r * ATTN_P + dd] = vbase[(size_t)(j0 + r) * RS + dd];
        }
        __syncthreads();

        float acc[4][4];
        #pragma unroll
        for (int i = 0; i < 4; i++)
            #pragma unroll
            for (int j = 0; j < 4; j++) acc[i][j] = 0.f;
        const float* qp = Qs + (4 * ty) * ATTN_P;
        const float* kp = Ks + (4 * tx) * ATTN_P;
        #pragma unroll 4
        for (int dd = 0; dd < 64; dd++) {
            float q0v = qp[dd], q1v = qp[ATTN_P + dd],
                  q2v = qp[2 * ATTN_P + dd], q3v = qp[3 * ATTN_P + dd];
            float k0v = kp[dd], k1v = kp[ATTN_P + dd],
                  k2v = kp[2 * ATTN_P + dd], k3v = kp[3 * ATTN_P + dd];
            acc[0][0] += q0v * k0v; acc[0][1] += q0v * k1v; acc[0][2] += q0v * k2v; acc[0][3] += q0v * k3v;
            acc[1][0] += q1v * k0v; acc[1][1] += q1v * k1v; acc[1][2] += q1v * k2v; acc[1][3] += q1v * k3v;
            acc[2][0] += q2v * k0v; acc[2][1] += q2v * k1v; acc[2][2] += q2v * k2v; acc[2][3] += q2v * k3v;
            acc[3][0] += q3v * k0v; acc[3][1] += q3v * k1v; acc[3][2] += q3v * k2v; acc[3][3] += q3v * k3v;
        }
        #pragma unroll
        for (int i = 0; i < 4; i++) {
            int qq = q0 + 4 * ty + i;
            #pragma unroll
            for (int j = 0; j < 4; j++) {
                int kk = j0 + 4 * tx + j;
                float s = acc[i][j] * scale;
                if (kk > qq) s = -1e30f;
                Ss[(4 * ty + i) * ATTN_P + 4 * tx + j] = s;
            }
        }
        __syncthreads();

        if (tid < 64) {
            int r = tid;
            float mold = m_s[r];
            float mx = mold;
            float* srow = Ss + r * ATTN_P;
            #pragma unroll 8
            for (int k = 0; k < 64; k++) mx = fmaxf(mx, srow[k]);
            float fac = __expf(mold - mx);
            float l = l_s[r] * fac;
            #pragma unroll 8
            for (int k = 0; k < 64; k++) {
                float p = __expf(srow[k] - mx);
                srow[k] = p;
                l += p;
            }
            m_s[r] = mx; l_s[r] = l; f_s[r] = fac;
        }
        __syncthreads();

        #pragma unroll
        for (int i = 0; i < 4; i++) {
            float f = f_s[4 * ty + i];
            #pragma unroll
            for (int j = 0; j < 4; j++) o[i][j] *= f;
        }
        const float* sp = Ss + (4 * ty) * ATTN_P;
        #pragma unroll 4
        for (int k = 0; k < 64; k++) {
            float p0 = sp[k], p1 = sp[ATTN_P + k],
                  p2 = sp[2 * ATTN_P + k], p3 = sp[3 * ATTN_P + k];
            const float* vrow = Vs + k * ATTN_P + 4 * tx;
            float v0 = vrow[0], v1 = vrow[1], v2 = vrow[2], v3 = vrow[3];
            o[0][0] += p0 * v0; o[0][1] += p0 * v1; o[0][2] += p0 * v2; o[0][3] += p0 * v3;
            o[1][0] += p1 * v0; o[1][1] += p1 * v1; o[1][2] += p1 * v2; o[1][3] += p1 * v3;
            o[2][0] += p2 * v0; o[2][1] += p2 * v1; o[2][2] += p2 * v2; o[2][3] += p2 * v3;
            o[3][0] += p3 * v0; o[3][1] += p3 * v1; o[3][2] += p3 * v2; o[3][3] += p3 * v3;
        }
        __syncthreads();
    }

    #pragma unroll
    for (int i = 0; i < 4; i++) {
        float inv = 1.f / l_s[4 * ty + i];
        size_t orow = (size_t)(b * TLEN + q0 + 4 * ty + i) * DMODEL + h * HDIM + 4 * tx;
        #pragma unroll
        for (int j = 0; j < 4; j++)
            out[orow + j] = o[i][j] * inv;
    }
}

#define ATTN_SMEM ((4 * 64 * ATTN_P + 3 * 64) * (int)sizeof(float))

// ---------------- driver ----------------------------------------------------
extern "C" void kernel_launch(void* const* d_in, const int* in_sizes, int n_in,
                              void* d_out, int out_size) {
    const float* wte    = (const float*)d_in[0];
    const float* wpe    = (const float*)d_in[1];
    const float* ln1_w  = (const float*)d_in[2];
    const float* ln1_b  = (const float*)d_in[3];
    const float* attn_w = (const float*)d_in[4];
    const float* attn_b = (const float*)d_in[5];
    const float* proj_w = (const float*)d_in[6];
    const float* proj_b = (const float*)d_in[7];
    const float* ln2_w  = (const float*)d_in[8];
    const float* ln2_b  = (const float*)d_in[9];
    const float* fc_w   = (const float*)d_in[10];
    const float* fc_b   = (const float*)d_in[11];
    const float* fc2_w  = (const float*)d_in[12];
    const float* fc2_b  = (const float*)d_in[13];
    const float* lnf_w  = (const float*)d_in[14];
    const float* lnf_b  = (const float*)d_in[15];
    const int*   idx    = (const int*)d_in[16];
    float* out = (float*)d_out;

    void *px, *ph, *pqkv, *patt, *pfc;
    cudaGetSymbolAddress(&px, g_x);
    cudaGetSymbolAddress(&ph, g_h);
    cudaGetSymbolAddress(&pqkv, g_qkv);
    cudaGetSymbolAddress(&patt, g_att);
    cudaGetSymbolAddress(&pfc, g_fc);
    float* x   = (float*)px;
    float* h   = (float*)ph;
    float* qkv = (float*)pqkv;
    float* att = (float*)patt;
    float* fcb = (float*)pfc;

    cudaFuncSetAttribute(attn_kernel,
                         cudaFuncAttributeMaxDynamicSharedMemorySize, ATTN_SMEM);

    embed_kernel<<<MROWS, 256>>>(wte, wpe, idx, x);

    for (int l = 0; l < NLAYER; l++) {
        const float* aw  = attn_w + (size_t)l * DMODEL * 3 * DMODEL;
        const float* ab  = attn_b + (size_t)l * 3 * DMODEL;
        const float* pw  = proj_w + (size_t)l * DMODEL * DMODEL;
        const float* pb  = proj_b + (size_t)l * DMODEL;
        const float* fw  = fc_w   + (size_t)l * DMODEL * 4 * DMODEL;
        const float* fb  = fc_b   + (size_t)l * 4 * DMODEL;
        const float* f2w = fc2_w  + (size_t)l * 4 * DMODEL * DMODEL;
        const float* f2b = fc2_b  + (size_t)l * DMODEL;

        ln_kernel<<<MROWS, 256>>>(x, ln1_w + l * DMODEL, ln1_b + l * DMODEL, h);
        gemm_tf32<false><<<dim3(3 * DMODEL / 128, MROWS / 128), 256>>>(
            h, aw, ab, nullptr, qkv, MROWS, 3 * DMODEL, DMODEL, 0);
        attn_kernel<<<dim3(TLEN / 64, BATCH * NHEAD), 256, ATTN_SMEM>>>(qkv, att);
        gemm_tf32<false><<<dim3(DMODEL / 128, MROWS / 128), 256>>>(
            att, pw, pb, x, x, MROWS, DMODEL, DMODEL, 0);
        ln_kernel<<<MROWS, 256>>>(x, ln2_w + l * DMODEL, ln2_b + l * DMODEL, h);
        gemm_tf32<false><<<dim3(4 * DMODEL / 128, MROWS / 128), 256>>>(
            h, fw, fb, nullptr, fcb, MROWS, 4 * DMODEL, DMODEL, 1);
        gemm_tf32<false><<<dim3(DMODEL / 128, MROWS / 128), 256>>>(
            fcb, f2w, f2b, x, x, MROWS, DMODEL, 4 * DMODEL, 0);
    }

    ln_kernel<<<MROWS, 256>>>(x, lnf_w, lnf_b, h);
    gemm_tf32<true><<<dim3(VOCAB / 128, MROWS / 128), 256>>>(
        h, wte, nullptr, nullptr, out, MROWS, VOCAB, DMODEL, 0);
}

// round 3
// speedup vs baseline: 2.3765x; 1.2272x over previous
#include <cuda_runtime.h>
#include <math.h>
#include <stdint.h>

// ---------------- problem constants ----------------
#define NLAYER 4
#define NHEAD  8
#define DMODEL 512
#define TLEN   2048
#define BATCH  2
#define VOCAB  32000
#define HDIM   64
#define MROWS  (BATCH * TLEN)   // 4096
#define EPS    1e-5f

// ---------------- scratch (static device globals; no allocs allowed) -------
__device__ float g_x  [MROWS * DMODEL];
__device__ float g_h  [MROWS * DMODEL];
__device__ float g_qkv[MROWS * 3 * DMODEL];
__device__ float g_att[MROWS * DMODEL];
__device__ float g_fc [MROWS * 4 * DMODEL];

// ---------------- embedding ----------------
__global__ void embed_kernel(const float* __restrict__ wte,
                             const float* __restrict__ wpe,
                             const int*   __restrict__ idx,
                             float* __restrict__ x) {
    int m = blockIdx.x;
    int t = m % TLEN;
    int tok = idx[m];
    const float* we = wte + (size_t)tok * DMODEL;
    const float* pe = wpe + (size_t)t * DMODEL;
    float* xr = x + (size_t)m * DMODEL;
    for (int d = threadIdx.x; d < DMODEL; d += blockDim.x)
        xr[d] = we[d] + pe[d];
}

// ---------------- layernorm ----------------
__global__ __launch_bounds__(256)
void ln_kernel(const float* __restrict__ x, const float* __restrict__ w,
               const float* __restrict__ b, float* __restrict__ y) {
    int row = blockIdx.x;
    int tid = threadIdx.x;
    const float* xr = x + (size_t)row * DMODEL;
    float v0 = xr[tid];
    float v1 = xr[tid + 256];

    __shared__ float red[8];
    __shared__ float bc;

    float s = v0 + v1;
    #pragma unroll
    for (int o = 16; o; o >>= 1) s += __shfl_xor_sync(0xffffffffu, s, o);
    if ((tid & 31) == 0) red[tid >> 5] = s;
    __syncthreads();
    if (tid == 0) {
        float t = 0.f;
        #pragma unroll
        for (int i = 0; i < 8; i++) t += red[i];
        bc = t;
    }
    __syncthreads();
    float mu = bc * (1.f / DMODEL);
    float d0 = v0 - mu, d1 = v1 - mu;

    float s2 = d0 * d0 + d1 * d1;
    #pragma unroll
    for (int o = 16; o; o >>= 1) s2 += __shfl_xor_sync(0xffffffffu, s2, o);
    __syncthreads();
    if ((tid & 31) == 0) red[tid >> 5] = s2;
    __syncthreads();
    if (tid == 0) {
        float t = 0.f;
        #pragma unroll
        for (int i = 0; i < 8; i++) t += red[i];
        bc = t;
    }
    __syncthreads();
    float inv = rsqrtf(bc * (1.f / DMODEL) + EPS);

    float* yr = y + (size_t)row * DMODEL;
    yr[tid]       = d0 * inv * w[tid]       + b[tid];
    yr[tid + 256] = d1 * inv * w[tid + 256] + b[tid + 256];
}

// ---------------- tf32 helpers ----------------------------------------------
__device__ __forceinline__ uint32_t f2tf32(float v) {
    uint32_t r;
    asm("cvt.rna.tf32.f32 %0, %1;" : "=r"(r) : "f"(v));
    return r;
}

__device__ __forceinline__ void mma_tf32(float* d, const uint32_t* a, const uint32_t* b) {
    asm volatile(
        "mma.sync.aligned.m16n8k8.row.col.f32.tf32.tf32.f32 "
        "{%0,%1,%2,%3},{%4,%5,%6,%7},{%8,%9},{%0,%1,%2,%3};\n"
        : "+f"(d[0]), "+f"(d[1]), "+f"(d[2]), "+f"(d[3])
        : "r"(a[0]), "r"(a[1]), "r"(a[2]), "r"(a[3]), "r"(b[0]), "r"(b[1]));
}

// ---------------- tf32 tensor-core GEMM -------------------------------------
#define AP 20
#define BP 136
template<bool BTRANS>
__global__ __launch_bounds__(256)
void gemm_tf32(const float* __restrict__ A, const float* __restrict__ Bm,
               const float* __restrict__ bias, const float* __restrict__ resid,
               float* __restrict__ Cm, int M, int N, int K, int gelu_flag) {
    __shared__ uint32_t As[128 * AP];
    __shared__ uint32_t Bs[16 * BP];

    int tid  = threadIdx.x;
    int lane = tid & 31;
    int w    = tid >> 5;
    int g    = lane >> 2;
    int tig  = lane & 3;
    int wm   = (w >> 2) * 64;
    int wn   = (w & 3) * 32;
    // lm-head (BTRANS) swaps grid axes so a wave of CTAs reuses B tiles in L2.
    int m0 = (BTRANS ? blockIdx.x : blockIdx.y) * 128;
    int n0 = (BTRANS ? blockIdx.y : blockIdx.x) * 128;

    float d[4][4][4];
    #pragma unroll
    for (int i = 0; i < 4; i++)
        #pragma unroll
        for (int j = 0; j < 4; j++)
            #pragma unroll
            for (int r = 0; r < 4; r++) d[i][j][r] = 0.f;

    for (int k0 = 0; k0 < K; k0 += 16) {
        #pragma unroll
        for (int s = 0; s < 2; s++) {
            int idx = tid + s * 256;
            int r = idx >> 2;
            int c = (idx & 3) * 4;
            float4 av = *(const float4*)&A[(size_t)(m0 + r) * K + k0 + c];
            As[r * AP + c + 0] = f2tf32(av.x);
            As[r * AP + c + 1] = f2tf32(av.y);
            As[r * AP + c + 2] = f2tf32(av.z);
            As[r * AP + c + 3] = f2tf32(av.w);
        }
        if (!BTRANS) {
            #pragma unroll
            for (int s = 0; s < 2; s++) {
                int idx = tid + s * 256;
                int r  = idx >> 5;
                int c4 = idx & 31;
                float4 bv = *(const float4*)&Bm[(size_t)(k0 + r) * N + n0 + c4 * 4];
                uint32_t* p = &Bs[r * BP + c4 * 4];
                p[0] = f2tf32(bv.x); p[1] = f2tf32(bv.y);
                p[2] = f2tf32(bv.z); p[3] = f2tf32(bv.w);
            }
        } else {
            #pragma unroll
            for (int s = 0; s < 2; s++) {
                int idx = tid + s * 256;
                int r = idx >> 2;
                int c = (idx & 3) * 4;
                float4 bv = *(const float4*)&Bm[(size_t)(n0 + r) * K + k0 + c];
                Bs[(c + 0) * BP + r] = f2tf32(bv.x);
                Bs[(c + 1) * BP + r] = f2tf32(bv.y);
                Bs[(c + 2) * BP + r] = f2tf32(bv.z);
                Bs[(c + 3) * BP + r] = f2tf32(bv.w);
            }
        }
        __syncthreads();

        #pragma unroll
        for (int kk = 0; kk < 16; kk += 8) {
            uint32_t af[4][4];
            #pragma unroll
            for (int mi = 0; mi < 4; mi++) {
                int rb = wm + mi * 16;
                af[mi][0] = As[(rb + g    ) * AP + kk + tig    ];
                af[mi][1] = As[(rb + g + 8) * AP + kk + tig    ];
                af[mi][2] = As[(rb + g    ) * AP + kk + tig + 4];
                af[mi][3] = As[(rb + g + 8) * AP + kk + tig + 4];
            }
            uint32_t bf[4][2];
            #pragma unroll
            for (int nj = 0; nj < 4; nj++) {
                int cb = wn + nj * 8;
                bf[nj][0] = Bs[(kk + tig    ) * BP + cb + g];
                bf[nj][1] = Bs[(kk + tig + 4) * BP + cb + g];
            }
            #pragma unroll
            for (int mi = 0; mi < 4; mi++)
                #pragma unroll
                for (int nj = 0; nj < 4; nj++)
                    mma_tf32(d[mi][nj], af[mi], bf[nj]);
        }
        __syncthreads();
    }

    #pragma unroll
    for (int mi = 0; mi < 4; mi++) {
        #pragma unroll
        for (int rr = 0; rr < 2; rr++) {
            int m = m0 + wm + mi * 16 + g + rr * 8;
            float* crow = Cm + (size_t)m * N;
            const float* rrow = resid ? resid + (size_t)m * N : nullptr;
            #pragma unroll
            for (int nj = 0; nj < 4; nj++) {
                int n = n0 + wn + nj * 8 + tig * 2;
                #pragma unroll
                for (int cc = 0; cc < 2; cc++) {
                    float c = d[mi][nj][rr * 2 + cc];
                    if (bias) c += bias[n + cc];
                    if (rrow) c += rrow[n + cc];
                    if (gelu_flag)
                        c = 0.5f * c * (1.f + erff(c * 0.70710678118654752f));
                    crow[n + cc] = c;
                }
            }
        }
    }
}

// ---------------- tensor-core causal flash attention -------------------------
// 64 q-rows per block, 4 warps x 16 rows (one m16 tile each).
// QK^T in split-tf32 (3 MMAs: hi*hi + lo*hi + hi*lo) => ~fp32-accurate scores.
// P*V in single tf32. Softmax fully in registers, quad-lane shfl reductions.
// Smem pitch 72 makes every fragment address pattern (g*8+tig / tig*8+g)
// cover all 32 banks conflict-free.
#define AT_P 72
#define ATTN_SMEM_TC (6 * 64 * AT_P * (int)sizeof(uint32_t))  // 110592 B

__global__ __launch_bounds__(128)
void attn_tc_kernel(const float* __restrict__ qkv, float* __restrict__ out) {
    extern __shared__ uint32_t smu[];
    uint32_t* Qh = smu;
    uint32_t* Ql = Qh + 64 * AT_P;
    uint32_t* Kh = Ql + 64 * AT_P;
    uint32_t* Kl = Kh + 64 * AT_P;
    uint32_t* Vt = Kl + 64 * AT_P;
    uint32_t* Ps = Vt + 64 * AT_P;

    int tid  = threadIdx.x;
    int lane = tid & 31;
    int wid  = tid >> 5;
    int g    = lane >> 2;
    int tig  = lane & 3;
    int b = blockIdx.y >> 3, h = blockIdx.y & 7;
    int q0 = blockIdx.x * 64;
    const int RS = 3 * DMODEL;
    const float* qbase = qkv + (size_t)b * TLEN * RS + h * HDIM;
    const float* kbase = qbase + DMODEL;
    const float* vbase = qbase + 2 * DMODEL;

    // Q tile: scale by 1/sqrt(64) then split into tf32 hi/lo
    for (int i = tid; i < 64 * 16; i += 128) {
        int r = i >> 4, d4 = (i & 15) * 4;
        float4 v = *(const float4*)&qbase[(size_t)(q0 + r) * RS + d4];
        float q4[4] = {v.x, v.y, v.z, v.w};
        #pragma unroll
        for (int c = 0; c < 4; c++) {
            float qs = q4[c] * 0.125f;
            uint32_t hi = f2tf32(qs);
            Qh[r * AT_P + d4 + c] = hi;
            Ql[r * AT_P + d4 + c] = f2tf32(qs - __uint_as_float(hi));
        }
    }

    float o[8][4];
    #pragma unroll
    for (int nj = 0; nj < 8; nj++)
        #pragma unroll
        for (int c = 0; c < 4; c++) o[nj][c] = 0.f;
    float m0 = -1e30f, m1 = -1e30f, l0 = 0.f, l1 = 0.f;
    int wrow = wid * 16;
    int rowA = wrow + g, rowB = wrow + g + 8;

    for (int j0 = 0; j0 <= q0; j0 += 64) {
        __syncthreads();   // all warps done with previous K/V before overwrite
        for (int i = tid; i < 64 * 16; i += 128) {
            int r = i >> 4, d4 = (i & 15) * 4;
            float4 kv = *(const float4*)&kbase[(size_t)(j0 + r) * RS + d4];
            float4 vv = *(const float4*)&vbase[(size_t)(j0 + r) * RS + d4];
            float k4[4] = {kv.x, kv.y, kv.z, kv.w};
            float v4[4] = {vv.x, vv.y, vv.z, vv.w};
            #pragma unroll
            for (int c = 0; c < 4; c++) {
                uint32_t hi = f2tf32(k4[c]);
                Kh[r * AT_P + d4 + c] = hi;
                Kl[r * AT_P + d4 + c] = f2tf32(k4[c] - __uint_as_float(hi));
                Vt[r * AT_P + d4 + c] = f2tf32(v4[c]);
            }
        }
        __syncthreads();

        // ---- S = Q K^T (split-tf32) ----
        float s[8][4];
        #pragma unroll
        for (int nj = 0; nj < 8; nj++)
            #pragma unroll
            for (int c = 0; c < 4; c++) s[nj][c] = 0.f;

        #pragma unroll
        for (int k8 = 0; k8 < 64; k8 += 8) {
            uint32_t ah[4], al[4];
            ah[0] = Qh[rowA * AT_P + k8 + tig];
            ah[1] = Qh[rowB * AT_P + k8 + tig];
            ah[2] = Qh[rowA * AT_P + k8 + tig + 4];
            ah[3] = Qh[rowB * AT_P + k8 + tig + 4];
            al[0] = Ql[rowA * AT_P + k8 + tig];
            al[1] = Ql[rowB * AT_P + k8 + tig];
            al[2] = Ql[rowA * AT_P + k8 + tig + 4];
            al[3] = Ql[rowB * AT_P + k8 + tig + 4];
            #pragma unroll
            for (int nj = 0; nj < 8; nj++) {
                int kr = nj * 8 + g;
                uint32_t bh2[2] = {Kh[kr * AT_P + k8 + tig], Kh[kr * AT_P + k8 + tig + 4]};
                uint32_t bl2[2] = {Kl[kr * AT_P + k8 + tig], Kl[kr * AT_P + k8 + tig + 4]};
                mma_tf32(s[nj], ah, bh2);
                mma_tf32(s[nj], al, bh2);
                mma_tf32(s[nj], ah, bl2);
            }
        }

        // ---- causal mask (only the diagonal tile) ----
        if (j0 == q0) {
            #pragma unroll
            for (int nj = 0; nj < 8; nj++) {
                int k0c = nj * 8 + 2 * tig;
                if (k0c     > rowA) s[nj][0] = -1e30f;
                if (k0c + 1 > rowA) s[nj][1] = -1e30f;
                if (k0c     > rowB) s[nj][2] = -1e30f;
                if (k0c + 1 > rowB) s[nj][3] = -1e30f;
            }
        }

        // ---- online softmax (registers + quad shfl) ----
        float mx0 = m0, mx1 = m1;
        #pragma unroll
        for (int nj = 0; nj < 8; nj++) {
            mx0 = fmaxf(mx0, fmaxf(s[nj][0], s[nj][1]));
            mx1 = fmaxf(mx1, fmaxf(s[nj][2], s[nj][3]));
        }
        mx0 = fmaxf(mx0, __shfl_xor_sync(0xffffffffu, mx0, 1));
        mx0 = fmaxf(mx0, __shfl_xor_sync(0xffffffffu, mx0, 2));
        mx1 = fmaxf(mx1, __shfl_xor_sync(0xffffffffu, mx1, 1));
        mx1 = fmaxf(mx1, __shfl_xor_sync(0xffffffffu, mx1, 2));

        float fac0 = __expf(m0 - mx0), fac1 = __expf(m1 - mx1);
        float sum0 = 0.f, sum1 = 0.f;
        #pragma unroll
        for (int nj = 0; nj < 8; nj++) {
            float p0 = __expf(s[nj][0] - mx0);
            float p1 = __expf(s[nj][1] - mx0);
            float p2 = __expf(s[nj][2] - mx1);
            float p3 = __expf(s[nj][3] - mx1);
            sum0 += p0 + p1; sum1 += p2 + p3;
            int cc = nj * 8 + 2 * tig;
            Ps[rowA * AT_P + cc]     = f2tf32(p0);
            Ps[rowA * AT_P + cc + 1] = f2tf32(p1);
            Ps[rowB * AT_P + cc]     = f2tf32(p2);
            Ps[rowB * AT_P + cc + 1] = f2tf32(p3);
        }
        sum0 += __shfl_xor_sync(0xffffffffu, sum0, 1);
        sum0 += __shfl_xor_sync(0xffffffffu, sum0, 2);
        sum1 += __shfl_xor_sync(0xffffffffu, sum1, 1);
        sum1 += __shfl_xor_sync(0xffffffffu, sum1, 2);
        l0 = l0 * fac0 + sum0;
        l1 = l1 * fac1 + sum1;
        m0 = mx0; m1 = mx1;
        #pragma unroll
        for (int nj = 0; nj < 8; nj++) {
            o[nj][0] *= fac0; o[nj][1] *= fac0;
            o[nj][2] *= fac1; o[nj][3] *= fac1;
        }
        __syncwarp();   // Ps writes visible across the warp before frag loads

        // ---- O += P V (single tf32; P rows are warp-private) ----
        #pragma unroll
        for (int k8 = 0; k8 < 64; k8 += 8) {
            uint32_t a[4];
            a[0] = Ps[rowA * AT_P + k8 + tig];
            a[1] = Ps[rowB * AT_P + k8 + tig];
            a[2] = Ps[rowA * AT_P + k8 + tig + 4];
            a[3] = Ps[rowB * AT_P + k8 + tig + 4];
            #pragma unroll
            for (int nj = 0; nj < 8; nj++) {
                uint32_t bv[2] = {Vt[(k8 + tig) * AT_P + nj * 8 + g],
                                  Vt[(k8 + tig + 4) * AT_P + nj * 8 + g]};
                mma_tf32(o[nj], a, bv);
            }
        }
    }

    float inv0 = 1.f / l0, inv1 = 1.f / l1;
    size_t rA = (size_t)(b * TLEN + q0 + rowA) * DMODEL + h * HDIM;
    size_t rB = (size_t)(b * TLEN + q0 + rowB) * DMODEL + h * HDIM;
    #pragma unroll
    for (int nj = 0; nj < 8; nj++) {
        int cc = nj * 8 + 2 * tig;
        out[rA + cc]     = o[nj][0] * inv0;
        out[rA + cc + 1] = o[nj][1] * inv0;
        out[rB + cc]     = o[nj][2] * inv1;
        out[rB + cc + 1] = o[nj][3] * inv1;
    }
}

// ---------------- driver ----------------------------------------------------
extern "C" void kernel_launch(void* const* d_in, const int* in_sizes, int n_in,
                              void* d_out, int out_size) {
    const float* wte    = (const float*)d_in[0];
    const float* wpe    = (const float*)d_in[1];
    const float* ln1_w  = (const float*)d_in[2];
    const float* ln1_b  = (const float*)d_in[3];
    const float* attn_w = (const float*)d_in[4];
    const float* attn_b = (const float*)d_in[5];
    const float* proj_w = (const float*)d_in[6];
    const float* proj_b = (const float*)d_in[7];
    const float* ln2_w  = (const float*)d_in[8];
    const float* ln2_b  = (const float*)d_in[9];
    const float* fc_w   = (const float*)d_in[10];
    const float* fc_b   = (const float*)d_in[11];
    const float* fc2_w  = (const float*)d_in[12];
    const float* fc2_b  = (const float*)d_in[13];
    const float* lnf_w  = (const float*)d_in[14];
    const float* lnf_b  = (const float*)d_in[15];
    const int*   idx    = (const int*)d_in[16];
    float* out = (float*)d_out;

    void *px, *ph, *pqkv, *patt, *pfc;
    cudaGetSymbolAddress(&px, g_x);
    cudaGetSymbolAddress(&ph, g_h);
    cudaGetSymbolAddress(&pqkv, g_qkv);
    cudaGetSymbolAddress(&patt, g_att);
    cudaGetSymbolAddress(&pfc, g_fc);
    float* x   = (float*)px;
    float* h   = (float*)ph;
    float* qkv = (float*)pqkv;
    float* att = (float*)patt;
    float* fcb = (float*)pfc;

    cudaFuncSetAttribute(attn_tc_kernel,
                         cudaFuncAttributeMaxDynamicSharedMemorySize, ATTN_SMEM_TC);

    embed_kernel<<<MROWS, 256>>>(wte, wpe, idx, x);

    for (int l = 0; l < NLAYER; l++) {
        const float* aw  = attn_w + (size_t)l * DMODEL * 3 * DMODEL;
        const float* ab  = attn_b + (size_t)l * 3 * DMODEL;
        const float* pw  = proj_w + (size_t)l * DMODEL * DMODEL;
        const float* pb  = proj_b + (size_t)l * DMODEL;
        const float* fw  = fc_w   + (size_t)l * DMODEL * 4 * DMODEL;
        const float* fb  = fc_b   + (size_t)l * 4 * DMODEL;
        const float* f2w = fc2_w  + (size_t)l * 4 * DMODEL * DMODEL;
        const float* f2b = fc2_b  + (size_t)l * DMODEL;

        ln_kernel<<<MROWS, 256>>>(x, ln1_w + l * DMODEL, ln1_b + l * DMODEL, h);
        gemm_tf32<false><<<dim3(3 * DMODEL / 128, MROWS / 128), 256>>>(
            h, aw, ab, nullptr, qkv, MROWS, 3 * DMODEL, DMODEL, 0);
        attn_tc_kernel<<<dim3(TLEN / 64, BATCH * NHEAD), 128, ATTN_SMEM_TC>>>(qkv, att);
        gemm_tf32<false><<<dim3(DMODEL / 128, MROWS / 128), 256>>>(
            att, pw, pb, x, x, MROWS, DMODEL, DMODEL, 0);
        ln_kernel<<<MROWS, 256>>>(x, ln2_w + l * DMODEL, ln2_b + l * DMODEL, h);
        gemm_tf32<false><<<dim3(4 * DMODEL / 128, MROWS / 128), 256>>>(
            h, fw, fb, nullptr, fcb, MROWS, 4 * DMODEL, DMODEL, 1);
        gemm_tf32<false><<<dim3(DMODEL / 128, MROWS / 128), 256>>>(
            fcb, f2w, f2b, x, x, MROWS, DMODEL, 4 * DMODEL, 0);
    }

    ln_kernel<<<MROWS, 256>>>(x, lnf_w, lnf_b, h);
    // lm-head: grid swapped (x = M blocks, y = N blocks) for L2 reuse of wte
    gemm_tf32<true><<<dim3(MROWS / 128, VOCAB / 128), 256>>>(
        h, wte, nullptr, nullptr, out, MROWS, VOCAB, DMODEL, 0);
}

// round 4
// speedup vs baseline: 2.6344x; 1.1085x over previous
#include <cuda_runtime.h>
#include <math.h>
#include <stdint.h>

// ---------------- problem constants ----------------
#define NLAYER 4
#define NHEAD  8
#define DMODEL 512
#define TLEN   2048
#define BATCH  2
#define VOCAB  32000
#define HDIM   64
#define MROWS  (BATCH * TLEN)   // 4096
#define EPS    1e-5f

// ---------------- scratch (static device globals; no allocs allowed) -------
__device__ float g_x  [MROWS * DMODEL];
__device__ float g_h  [MROWS * DMODEL];
__device__ float g_qkv[MROWS * 3 * DMODEL];
__device__ float g_att[MROWS * DMODEL];
__device__ float g_fc [MROWS * 4 * DMODEL];

// ---------------- embedding ----------------
__global__ void embed_kernel(const float* __restrict__ wte,
                             const float* __restrict__ wpe,
                             const int*   __restrict__ idx,
                             float* __restrict__ x) {
    int m = blockIdx.x;
    int t = m % TLEN;
    int tok = idx[m];
    const float* we = wte + (size_t)tok * DMODEL;
    const float* pe = wpe + (size_t)t * DMODEL;
    float* xr = x + (size_t)m * DMODEL;
    for (int d = threadIdx.x; d < DMODEL; d += blockDim.x)
        xr[d] = we[d] + pe[d];
}

// ---------------- layernorm ----------------
__global__ __launch_bounds__(256)
void ln_kernel(const float* __restrict__ x, const float* __restrict__ w,
               const float* __restrict__ b, float* __restrict__ y) {
    int row = blockIdx.x;
    int tid = threadIdx.x;
    const float* xr = x + (size_t)row * DMODEL;
    float v0 = xr[tid];
    float v1 = xr[tid + 256];

    __shared__ float red[8];
    __shared__ float bc;

    float s = v0 + v1;
    #pragma unroll
    for (int o = 16; o; o >>= 1) s += __shfl_xor_sync(0xffffffffu, s, o);
    if ((tid & 31) == 0) red[tid >> 5] = s;
    __syncthreads();
    if (tid == 0) {
        float t = 0.f;
        #pragma unroll
        for (int i = 0; i < 8; i++) t += red[i];
        bc = t;
    }
    __syncthreads();
    float mu = bc * (1.f / DMODEL);
    float d0 = v0 - mu, d1 = v1 - mu;

    float s2 = d0 * d0 + d1 * d1;
    #pragma unroll
    for (int o = 16; o; o >>= 1) s2 += __shfl_xor_sync(0xffffffffu, s2, o);
    __syncthreads();
    if ((tid & 31) == 0) red[tid >> 5] = s2;
    __syncthreads();
    if (tid == 0) {
        float t = 0.f;
        #pragma unroll
        for (int i = 0; i < 8; i++) t += red[i];
        bc = t;
    }
    __syncthreads();
    float inv = rsqrtf(bc * (1.f / DMODEL) + EPS);

    float* yr = y + (size_t)row * DMODEL;
    yr[tid]       = d0 * inv * w[tid]       + b[tid];
    yr[tid + 256] = d1 * inv * w[tid + 256] + b[tid + 256];
}

// ---------------- tf32 helpers ----------------------------------------------
__device__ __forceinline__ uint32_t f2tf32(float v) {
    uint32_t r;
    asm("cvt.rna.tf32.f32 %0, %1;" : "=r"(r) : "f"(v));
    return r;
}

__device__ __forceinline__ void mma_tf32(float* d, const uint32_t* a, const uint32_t* b) {
    asm volatile(
        "mma.sync.aligned.m16n8k8.row.col.f32.tf32.tf32.f32 "
        "{%0,%1,%2,%3},{%4,%5,%6,%7},{%8,%9},{%0,%1,%2,%3};\n"
        : "+f"(d[0]), "+f"(d[1]), "+f"(d[2]), "+f"(d[3])
        : "r"(a[0]), "r"(a[1]), "r"(a[2]), "r"(a[3]), "r"(b[0]), "r"(b[1]));
}

// ---------------- pipelined tf32 tensor-core GEMM ----------------------------
// C[M,N] = A[M,K] @ B (+bias) (+resid) (opt gelu).
// Double-buffered smem; per iteration: issue next tile's LDGs, run MMAs on
// current buffer, cvt+store next buffer, ONE __syncthreads.
#define AP 20
#define BP 136
template<bool BTRANS>
__global__ __launch_bounds__(256)
void gemm_tf32(const float* __restrict__ A, const float* __restrict__ Bm,
               const float* __restrict__ bias, const float* __restrict__ resid,
               float* __restrict__ Cm, int M, int N, int K, int gelu_flag) {
    __shared__ uint32_t As[2][128 * AP];
    __shared__ uint32_t Bs[2][16 * BP];

    int tid  = threadIdx.x;
    int lane = tid & 31;
    int w    = tid >> 5;
    int g    = lane >> 2;
    int tig  = lane & 3;
    int wm   = (w >> 2) * 64;
    int wn   = (w & 3) * 32;
    int m0 = (BTRANS ? blockIdx.x : blockIdx.y) * 128;
    int n0 = (BTRANS ? blockIdx.y : blockIdx.x) * 128;

    // per-thread load coordinates (fixed across iterations)
    int aR0 = tid >> 2,            aC0 = (tid & 3) * 4;
    int aR1 = (tid + 256) >> 2,    aC1 = aC0;            // same (idx&3)
    int bKr0, bNc0, bKr1, bNc1;
    if (!BTRANS) { bKr0 = tid >> 5; bNc0 = (tid & 31) * 4;
                   bKr1 = (tid + 256) >> 5; bNc1 = bNc0; }
    else         { bKr0 = (tid & 3) * 4; bNc0 = tid >> 2;    // r=n-row, c=k
                   bKr1 = bKr0; bNc1 = (tid + 256) >> 2; }

    float4 arg0, arg1, brg0, brg1;

    auto load_tile = [&](int k0) {
        arg0 = *(const float4*)&A[(size_t)(m0 + aR0) * K + k0 + aC0];
        arg1 = *(const float4*)&A[(size_t)(m0 + aR1) * K + k0 + aC1];
        if (!BTRANS) {
            brg0 = *(const float4*)&Bm[(size_t)(k0 + bKr0) * N + n0 + bNc0];
            brg1 = *(const float4*)&Bm[(size_t)(k0 + bKr1) * N + n0 + bNc1];
        } else {
            brg0 = *(const float4*)&Bm[(size_t)(n0 + bNc0) * K + k0 + bKr0];
            brg1 = *(const float4*)&Bm[(size_t)(n0 + bNc1) * K + k0 + bKr1];
        }
    };
    auto store_tile = [&](int buf) {
        uint32_t* ap = &As[buf][aR0 * AP + aC0];
        ap[0] = f2tf32(arg0.x); ap[1] = f2tf32(arg0.y);
        ap[2] = f2tf32(arg0.z); ap[3] = f2tf32(arg0.w);
        ap = &As[buf][aR1 * AP + aC1];
        ap[0] = f2tf32(arg1.x); ap[1] = f2tf32(arg1.y);
        ap[2] = f2tf32(arg1.z); ap[3] = f2tf32(arg1.w);
        if (!BTRANS) {
            uint32_t* bp = &Bs[buf][bKr0 * BP + bNc0];
            bp[0] = f2tf32(brg0.x); bp[1] = f2tf32(brg0.y);
            bp[2] = f2tf32(brg0.z); bp[3] = f2tf32(brg0.w);
            bp = &Bs[buf][bKr1 * BP + bNc1];
            bp[0] = f2tf32(brg1.x); bp[1] = f2tf32(brg1.y);
            bp[2] = f2tf32(brg1.z); bp[3] = f2tf32(brg1.w);
        } else {
            Bs[buf][(bKr0 + 0) * BP + bNc0] = f2tf32(brg0.x);
            Bs[buf][(bKr0 + 1) * BP + bNc0] = f2tf32(brg0.y);
            Bs[buf][(bKr0 + 2) * BP + bNc0] = f2tf32(brg0.z);
            Bs[buf][(bKr0 + 3) * BP + bNc0] = f2tf32(brg0.w);
            Bs[buf][(bKr1 + 0) * BP + bNc1] = f2tf32(brg1.x);
            Bs[buf][(bKr1 + 1) * BP + bNc1] = f2tf32(brg1.y);
            Bs[buf][(bKr1 + 2) * BP + bNc1] = f2tf32(brg1.z);
            Bs[buf][(bKr1 + 3) * BP + bNc1] = f2tf32(brg1.w);
        }
    };

    float d[4][4][4];
    #pragma unroll
    for (int i = 0; i < 4; i++)
        #pragma unroll
        for (int j = 0; j < 4; j++)
            #pragma unroll
            for (int r = 0; r < 4; r++) d[i][j][r] = 0.f;

    load_tile(0);
    store_tile(0);
    __syncthreads();

    int buf = 0;
    for (int k0 = 0; k0 < K; k0 += 16) {
        int nk = k0 + 16;
        if (nk < K) load_tile(nk);          // LDGs overlap the MMAs below

        const uint32_t* Ac = As[buf];
        const uint32_t* Bc = Bs[buf];
        #pragma unroll
        for (int kk = 0; kk < 16; kk += 8) {
            uint32_t af[4][4];
            #pragma unroll
            for (int mi = 0; mi < 4; mi++) {
                int rb = wm + mi * 16;
                af[mi][0] = Ac[(rb + g    ) * AP + kk + tig    ];
                af[mi][1] = Ac[(rb + g + 8) * AP + kk + tig    ];
                af[mi][2] = Ac[(rb + g    ) * AP + kk + tig + 4];
                af[mi][3] = Ac[(rb + g + 8) * AP + kk + tig + 4];
            }
            uint32_t bf[4][2];
            #pragma unroll
            for (int nj = 0; nj < 4; nj++) {
                int cb = wn + nj * 8;
                bf[nj][0] = Bc[(kk + tig    ) * BP + cb + g];
                bf[nj][1] = Bc[(kk + tig + 4) * BP + cb + g];
            }
            #pragma unroll
            for (int mi = 0; mi < 4; mi++)
                #pragma unroll
                for (int nj = 0; nj < 4; nj++)
                    mma_tf32(d[mi][nj], af[mi], bf[nj]);
        }

        if (nk < K) store_tile(buf ^ 1);
        __syncthreads();
        buf ^= 1;
    }

    #pragma unroll
    for (int mi = 0; mi < 4; mi++) {
        #pragma unroll
        for (int rr = 0; rr < 2; rr++) {
            int m = m0 + wm + mi * 16 + g + rr * 8;
            float* crow = Cm + (size_t)m * N;
            const float* rrow = resid ? resid + (size_t)m * N : nullptr;
            #pragma unroll
            for (int nj = 0; nj < 4; nj++) {
                int n = n0 + wn + nj * 8 + tig * 2;
                #pragma unroll
                for (int cc = 0; cc < 2; cc++) {
                    float c = d[mi][nj][rr * 2 + cc];
                    if (bias) c += bias[n + cc];
                    if (rrow) c += rrow[n + cc];
                    if (gelu_flag)
                        c = 0.5f * c * (1.f + erff(c * 0.70710678118654752f));
                    crow[n + cc] = c;
                }
            }
        }
    }
}

// ---------------- tensor-core causal flash attention -------------------------
// Split-tf32 QK^T, tf32 PV, register softmax. Ps ALIASES the Kl buffer
// (Kl is dead after QK^T; a __syncthreads separates the phases), shrinking
// smem 110->90 KB so 2 CTAs/SM fit (occupancy 2x).
#define AT_P 72
#define ATTN_SMEM_TC (5 * 64 * AT_P * (int)sizeof(uint32_t))  // 92160 B

__global__ __launch_bounds__(128)
void attn_tc_kernel(const float* __restrict__ qkv, float* __restrict__ out) {
    extern __shared__ uint32_t smu[];
    uint32_t* Qh = smu;
    uint32_t* Ql = Qh + 64 * AT_P;
    uint32_t* Kh = Ql + 64 * AT_P;
    uint32_t* Kl = Kh + 64 * AT_P;
    uint32_t* Vt = Kl + 64 * AT_P;
    uint32_t* Ps = Kl;                      // alias: Kl dead after QK^T

    int tid  = threadIdx.x;
    int lane = tid & 31;
    int wid  = tid >> 5;
    int g    = lane >> 2;
    int tig  = lane & 3;
    int b = blockIdx.y >> 3, h = blockIdx.y & 7;
    int q0 = blockIdx.x * 64;
    const int RS = 3 * DMODEL;
    const float* qbase = qkv + (size_t)b * TLEN * RS + h * HDIM;
    const float* kbase = qbase + DMODEL;
    const float* vbase = qbase + 2 * DMODEL;

    for (int i = tid; i < 64 * 16; i += 128) {
        int r = i >> 4, d4 = (i & 15) * 4;
        float4 v = *(const float4*)&qbase[(size_t)(q0 + r) * RS + d4];
        float q4[4] = {v.x, v.y, v.z, v.w};
        #pragma unroll
        for (int c = 0; c < 4; c++) {
            float qs = q4[c] * 0.125f;
            uint32_t hi = f2tf32(qs);
            Qh[r * AT_P + d4 + c] = hi;
            Ql[r * AT_P + d4 + c] = f2tf32(qs - __uint_as_float(hi));
        }
    }

    float o[8][4];
    #pragma unroll
    for (int nj = 0; nj < 8; nj++)
        #pragma unroll
        for (int c = 0; c < 4; c++) o[nj][c] = 0.f;
    float m0 = -1e30f, m1 = -1e30f, l0 = 0.f, l1 = 0.f;
    int wrow = wid * 16;
    int rowA = wrow + g, rowB = wrow + g + 8;

    for (int j0 = 0; j0 <= q0; j0 += 64) {
        __syncthreads();   // prev iter's PV (Ps=Kl, Vt reads) done before refill
        for (int i = tid; i < 64 * 16; i += 128) {
            int r = i >> 4, d4 = (i & 15) * 4;
            float4 kv = *(const float4*)&kbase[(size_t)(j0 + r) * RS + d4];
            float4 vv = *(const float4*)&vbase[(size_t)(j0 + r) * RS + d4];
            float k4[4] = {kv.x, kv.y, kv.z, kv.w};
            float v4[4] = {vv.x, vv.y, vv.z, vv.w};
            #pragma unroll
            for (int c = 0; c < 4; c++) {
                uint32_t hi = f2tf32(k4[c]);
                Kh[r * AT_P + d4 + c] = hi;
                Kl[r * AT_P + d4 + c] = f2tf32(k4[c] - __uint_as_float(hi));
                Vt[r * AT_P + d4 + c] = f2tf32(v4[c]);
            }
        }
        __syncthreads();

        // ---- S = Q K^T (split-tf32) ----
        float s[8][4];
        #pragma unroll
        for (int nj = 0; nj < 8; nj++)
            #pragma unroll
            for (int c = 0; c < 4; c++) s[nj][c] = 0.f;

        #pragma unroll
        for (int k8 = 0; k8 < 64; k8 += 8) {
            uint32_t ah[4], al[4];
            ah[0] = Qh[rowA * AT_P + k8 + tig];
            ah[1] = Qh[rowB * AT_P + k8 + tig];
            ah[2] = Qh[rowA * AT_P + k8 + tig + 4];
            ah[3] = Qh[rowB * AT_P + k8 + tig + 4];
            al[0] = Ql[rowA * AT_P + k8 + tig];
            al[1] = Ql[rowB * AT_P + k8 + tig];
            al[2] = Ql[rowA * AT_P + k8 + tig + 4];
            al[3] = Ql[rowB * AT_P + k8 + tig + 4];
            #pragma unroll
            for (int nj = 0; nj < 8; nj++) {
                int kr = nj * 8 + g;
                uint32_t bh2[2] = {Kh[kr * AT_P + k8 + tig], Kh[kr * AT_P + k8 + tig + 4]};
                uint32_t bl2[2] = {Kl[kr * AT_P + k8 + tig], Kl[kr * AT_P + k8 + tig + 4]};
                mma_tf32(s[nj], ah, bh2);
                mma_tf32(s[nj], al, bh2);
                mma_tf32(s[nj], ah, bl2);
            }
        }

        if (j0 == q0) {
            #pragma unroll
            for (int nj = 0; nj < 8; nj++) {
                int k0c = nj * 8 + 2 * tig;
                if (k0c     > rowA) s[nj][0] = -1e30f;
                if (k0c + 1 > rowA) s[nj][1] = -1e30f;
                if (k0c     > rowB) s[nj][2] = -1e30f;
                if (k0c + 1 > rowB) s[nj][3] = -1e30f;
            }
        }

        // ---- online softmax in registers ----
        float mx0 = m0, mx1 = m1;
        #pragma unroll
        for (int nj = 0; nj < 8; nj++) {
            mx0 = fmaxf(mx0, fmaxf(s[nj][0], s[nj][1]));
            mx1 = fmaxf(mx1, fmaxf(s[nj][2], s[nj][3]));
        }
        mx0 = fmaxf(mx0, __shfl_xor_sync(0xffffffffu, mx0, 1));
        mx0 = fmaxf(mx0, __shfl_xor_sync(0xffffffffu, mx0, 2));
        mx1 = fmaxf(mx1, __shfl_xor_sync(0xffffffffu, mx1, 1));
        mx1 = fmaxf(mx1, __shfl_xor_sync(0xffffffffu, mx1, 2));

        float fac0 = __expf(m0 - mx0), fac1 = __expf(m1 - mx1);
        float sum0 = 0.f, sum1 = 0.f;
        #pragma unroll
        for (int nj = 0; nj < 8; nj++) {
            s[nj][0] = __expf(s[nj][0] - mx0);
            s[nj][1] = __expf(s[nj][1] - mx0);
            s[nj][2] = __expf(s[nj][2] - mx1);
            s[nj][3] = __expf(s[nj][3] - mx1);
            sum0 += s[nj][0] + s[nj][1];
            sum1 += s[nj][2] + s[nj][3];
        }
        sum0 += __shfl_xor_sync(0xffffffffu, sum0, 1);
        sum0 += __shfl_xor_sync(0xffffffffu, sum0, 2);
        sum1 += __shfl_xor_sync(0xffffffffu, sum1, 1);
        sum1 += __shfl_xor_sync(0xffffffffu, sum1, 2);
        l0 = l0 * fac0 + sum0;
        l1 = l1 * fac1 + sum1;
        m0 = mx0; m1 = mx1;
        #pragma unroll
        for (int nj = 0; nj < 8; nj++) {
            o[nj][0] *= fac0; o[nj][1] *= fac0;
            o[nj][2] *= fac1; o[nj][3] *= fac1;
        }

        __syncthreads();   // all warps' QK^T reads of Kl done before Ps writes
        #pragma unroll
        for (int nj = 0; nj < 8; nj++) {
            int cc = nj * 8 + 2 * tig;
            Ps[rowA * AT_P + cc]     = f2tf32(s[nj][0]);
            Ps[rowA * AT_P + cc + 1] = f2tf32(s[nj][1]);
            Ps[rowB * AT_P + cc]     = f2tf32(s[nj][2]);
            Ps[rowB * AT_P + cc + 1] = f2tf32(s[nj][3]);
        }
        __syncwarp();      // Ps rows are warp-private

        // ---- O += P V (single tf32) ----
        #pragma unroll
        for (int k8 = 0; k8 < 64; k8 += 8) {
            uint32_t a[4];
            a[0] = Ps[rowA * AT_P + k8 + tig];
            a[1] = Ps[rowB * AT_P + k8 + tig];
            a[2] = Ps[rowA * AT_P + k8 + tig + 4];
            a[3] = Ps[rowB * AT_P + k8 + tig + 4];
            #pragma unroll
            for (int nj = 0; nj < 8; nj++) {
                uint32_t bv[2] = {Vt[(k8 + tig) * AT_P + nj * 8 + g],
                                  Vt[(k8 + tig + 4) * AT_P + nj * 8 + g]};
                mma_tf32(o[nj], a, bv);
            }
        }
    }

    float inv0 = 1.f / l0, inv1 = 1.f / l1;
    size_t rA = (size_t)(b * TLEN + q0 + rowA) * DMODEL + h * HDIM;
    size_t rB = (size_t)(b * TLEN + q0 + rowB) * DMODEL + h * HDIM;
    #pragma unroll
    for (int nj = 0; nj < 8; nj++) {
        int cc = nj * 8 + 2 * tig;
        out[rA + cc]     = o[nj][0] * inv0;
        out[rA + cc + 1] = o[nj][1] * inv0;
        out[rB + cc]     = o[nj][2] * inv1;
        out[rB + cc + 1] = o[nj][3] * inv1;
    }
}

// ---------------- driver ----------------------------------------------------
extern "C" void kernel_launch(void* const* d_in, const int* in_sizes, int n_in,
                              void* d_out, int out_size) {
    const float* wte    = (const float*)d_in[0];
    const float* wpe    = (const float*)d_in[1];
    const float* ln1_w  = (const float*)d_in[2];
    const float* ln1_b  = (const float*)d_in[3];
    const float* attn_w = (const float*)d_in[4];
    const float* attn_b = (const float*)d_in[5];
    const float* proj_w = (const float*)d_in[6];
    const float* proj_b = (const float*)d_in[7];
    const float* ln2_w  = (const float*)d_in[8];
    const float* ln2_b  = (const float*)d_in[9];
    const float* fc_w   = (const float*)d_in[10];
    const float* fc_b   = (const float*)d_in[11];
    const float* fc2_w  = (const float*)d_in[12];
    const float* fc2_b  = (const float*)d_in[13];
    const float* lnf_w  = (const float*)d_in[14];
    const float* lnf_b  = (const float*)d_in[15];
    const int*   idx    = (const int*)d_in[16];
    float* out = (float*)d_out;

    void *px, *ph, *pqkv, *patt, *pfc;
    cudaGetSymbolAddress(&px, g_x);
    cudaGetSymbolAddress(&ph, g_h);
    cudaGetSymbolAddress(&pqkv, g_qkv);
    cudaGetSymbolAddress(&patt, g_att);
    cudaGetSymbolAddress(&pfc, g_fc);
    float* x   = (float*)px;
    float* h   = (float*)ph;
    float* qkv = (float*)pqkv;
    float* att = (float*)patt;
    float* fcb = (float*)pfc;

    cudaFuncSetAttribute(attn_tc_kernel,
                         cudaFuncAttributeMaxDynamicSharedMemorySize, ATTN_SMEM_TC);

    embed_kernel<<<MROWS, 256>>>(wte, wpe, idx, x);

    for (int l = 0; l < NLAYER; l++) {
        const float* aw  = attn_w + (size_t)l * DMODEL * 3 * DMODEL;
        const float* ab  = attn_b + (size_t)l * 3 * DMODEL;
        const float* pw  = proj_w + (size_t)l * DMODEL * DMODEL;
        const float* pb  = proj_b + (size_t)l * DMODEL;
        const float* fw  = fc_w   + (size_t)l * DMODEL * 4 * DMODEL;
        const float* fb  = fc_b   + (size_t)l * 4 * DMODEL;
        const float* f2w = fc2_w  + (size_t)l * 4 * DMODEL * DMODEL;
        const float* f2b = fc2_b  + (size_t)l * DMODEL;

        ln_kernel<<<MROWS, 256>>>(x, ln1_w + l * DMODEL, ln1_b + l * DMODEL, h);
        gemm_tf32<false><<<dim3(3 * DMODEL / 128, MROWS / 128), 256>>>(
            h, aw, ab, nullptr, qkv, MROWS, 3 * DMODEL, DMODEL, 0);
        attn_tc_kernel<<<dim3(TLEN / 64, BATCH * NHEAD), 128, ATTN_SMEM_TC>>>(qkv, att);
        gemm_tf32<false><<<dim3(DMODEL / 128, MROWS / 128), 256>>>(
            att, pw, pb, x, x, MROWS, DMODEL, DMODEL, 0);
        ln_kernel<<<MROWS, 256>>>(x, ln2_w + l * DMODEL, ln2_b + l * DMODEL, h);
        gemm_tf32<false><<<dim3(4 * DMODEL / 128, MROWS / 128), 256>>>(
            h, fw, fb, nullptr, fcb, MROWS, 4 * DMODEL, DMODEL, 1);
        gemm_tf32<false><<<dim3(DMODEL / 128, MROWS / 128), 256>>>(
            fcb, f2w, f2b, x, x, MROWS, DMODEL, 4 * DMODEL, 0);
    }

    ln_kernel<<<MROWS, 256>>>(x, lnf_w, lnf_b, h);
    gemm_tf32<true><<<dim3(MROWS / 128, VOCAB / 128), 256>>>(
        h, wte, nullptr, nullptr, out, MROWS, VOCAB, DMODEL, 0);
}